// round 2
// baseline (speedup 1.0000x reference)
#include <cuda_runtime.h>
#include <cuda_bf16.h>
#include <math.h>

#define BB 4
#define LL 2048
#define DD 512
#define KTOP 7

// ---------------- scratch (device globals; no allocation allowed) ----------
__device__ float g_part[BB * 16 * DD];          // partial sums of queries over t
__device__ float g_r[BB * DD];                  // r[b] = wk @ (qbar @ wq), pre-scaled
__device__ float g_mc[BB * LL];                 // mean_corr
__device__ float g_wt[BB * 8];                  // softmax weights (7 used)
__device__ int   g_dl[BB * 8];                  // delays (7 used)
__device__ float g_W[DD * DD];                  // W = wv @ wo
__device__ float g_vagg[(size_t)BB * LL * DD];  // blended values

// ---------------- K1: partial column-sums of queries ------------------------
// grid (B, 2, 16), block 256: block sums 128 t-rows for 256 d-columns
__global__ void k_qpart(const float* __restrict__ q) {
    int b = blockIdx.x, dchunk = blockIdx.y, ts = blockIdx.z;
    int d = dchunk * 256 + threadIdx.x;
    const float* base = q + (size_t)b * LL * DD + (size_t)(ts * 128) * DD + d;
    float s = 0.f;
#pragma unroll 8
    for (int t = 0; t < 128; ++t) s += base[(size_t)t * DD];
    g_part[(b * 16 + ts) * DD + d] = s;
}

// ---------------- K2: r[b] = wk @ (qbar @ wq) * 1/16384 ---------------------
// grid B, block 512
__global__ void k_rvec(const float* __restrict__ wq, const float* __restrict__ wk) {
    __shared__ float qb[DD];
    __shared__ float qs[DD];
    int b = blockIdx.x, tid = threadIdx.x;
    float s = 0.f;
#pragma unroll
    for (int p = 0; p < 16; ++p) s += g_part[(b * 16 + p) * DD + tid];
    qb[tid] = s;
    __syncthreads();
    float acc = 0.f;
    for (int c = 0; c < DD; ++c) acc += qb[c] * wq[(size_t)c * DD + tid];
    qs[tid] = acc;
    __syncthreads();
    const float4* wkr = (const float4*)(wk + (size_t)tid * DD);
    float r = 0.f;
#pragma unroll 4
    for (int d4 = 0; d4 < DD / 4; ++d4) {
        float4 v = wkr[d4];
        r += v.x * qs[d4 * 4] + v.y * qs[d4 * 4 + 1] + v.z * qs[d4 * 4 + 2] + v.w * qs[d4 * 4 + 3];
    }
    g_r[b * DD + tid] = r * (1.0f / (8.0f * 2048.0f));
}

// ---------------- K3: mean_corr[b,j] = keys[b,j,:] . r[b] -------------------
// grid (L/8, B), block 256 (8 warps, 1 j per warp)
__global__ void k_mc(const float* __restrict__ keys) {
    __shared__ float rs[DD];
    int b = blockIdx.y, tid = threadIdx.x;
    rs[tid] = g_r[b * DD + tid];
    rs[tid + 256] = g_r[b * DD + tid + 256];
    __syncthreads();
    int warp = tid >> 5, lane = tid & 31;
    int j = blockIdx.x * 8 + warp;
    const float* kr = keys + ((size_t)b * LL + j) * DD;
    float acc = 0.f;
#pragma unroll
    for (int i = 0; i < 16; ++i) acc += kr[lane + 32 * i] * rs[lane + 32 * i];
#pragma unroll
    for (int o = 16; o; o >>= 1) acc += __shfl_down_sync(0xffffffffu, acc, o);
    if (lane == 0) g_mc[b * LL + j] = acc;
}

// ---------------- K4: top-7 + softmax per batch ------------------------------
// grid B, block 256
__global__ void k_topk() {
    int b = blockIdx.x, tid = threadIdx.x;
    __shared__ float vals[LL];
    __shared__ float bv[256];
    __shared__ int bi[256];
    __shared__ float sel_v[KTOP];
    __shared__ int sel_i[KTOP];
    for (int i = tid; i < LL; i += 256) vals[i] = g_mc[b * LL + i];
    __syncthreads();
    for (int kk = 0; kk < KTOP; ++kk) {
        float best = -INFINITY;
        int besti = 0x7fffffff;
        for (int i = tid; i < LL; i += 256) {
            float v = vals[i];
            if (v > best || (v == best && i < besti)) { best = v; besti = i; }
        }
        bv[tid] = best; bi[tid] = besti;
        __syncthreads();
        for (int s = 128; s; s >>= 1) {
            if (tid < s) {
                if (bv[tid + s] > bv[tid] || (bv[tid + s] == bv[tid] && bi[tid + s] < bi[tid])) {
                    bv[tid] = bv[tid + s]; bi[tid] = bi[tid + s];
                }
            }
            __syncthreads();
        }
        if (tid == 0) { sel_v[kk] = bv[0]; sel_i[kk] = bi[0]; vals[bi[0]] = -INFINITY; }
        __syncthreads();
    }
    if (tid == 0) {
        float m = sel_v[0];  // iterative selection yields descending order
        float e[KTOP], ssum = 0.f;
#pragma unroll
        for (int i = 0; i < KTOP; ++i) { e[i] = expf(sel_v[i] - m); ssum += e[i]; }
        float inv = 1.0f / ssum;
#pragma unroll
        for (int i = 0; i < KTOP; ++i) { g_wt[b * 8 + i] = e[i] * inv; g_dl[b * 8 + i] = sel_i[i]; }
    }
}

// ---------------- GEMM core: C = A @ B (row-major), 128x64x16 tiles ----------
// block 256 threads, thread computes 8x4. Requires M%128==0, N%64==0, K%16==0.
__device__ __forceinline__ void gemm_core(const float* __restrict__ A,
                                          const float* __restrict__ Bm,
                                          float* __restrict__ Cm,
                                          int N, int Kdim) {
    __shared__ float As[16][128];
    __shared__ float Bs[16][64];
    int tid = threadIdx.x;
    int tx = tid & 15;       // N dir, 16 groups of 4 cols
    int ty = tid >> 4;       // M dir, 16 groups of 8 rows
    int rowBase = blockIdx.y * 128;
    int colBase = blockIdx.x * 64;
    float acc[8][4];
#pragma unroll
    for (int i = 0; i < 8; ++i)
#pragma unroll
        for (int j = 0; j < 4; ++j) acc[i][j] = 0.f;

    for (int k0 = 0; k0 < Kdim; k0 += 16) {
#pragma unroll
        for (int i = 0; i < 2; ++i) {
            int lin = tid + i * 256;
            int r = lin >> 2;
            int c4 = (lin & 3) * 4;
            float4 v = *(const float4*)(A + (size_t)(rowBase + r) * Kdim + k0 + c4);
            As[c4][r] = v.x; As[c4 + 1][r] = v.y; As[c4 + 2][r] = v.z; As[c4 + 3][r] = v.w;
        }
        {
            int r = tid >> 4;
            int c4 = (tid & 15) * 4;
            *(float4*)&Bs[r][c4] = *(const float4*)(Bm + (size_t)(k0 + r) * N + colBase + c4);
        }
        __syncthreads();
#pragma unroll
        for (int k = 0; k < 16; ++k) {
            float4 a0 = *(const float4*)&As[k][ty * 8];
            float4 a1 = *(const float4*)&As[k][ty * 8 + 4];
            float4 b0 = *(const float4*)&Bs[k][tx * 4];
            float a[8] = {a0.x, a0.y, a0.z, a0.w, a1.x, a1.y, a1.z, a1.w};
            float bb[4] = {b0.x, b0.y, b0.z, b0.w};
#pragma unroll
            for (int im = 0; im < 8; ++im)
#pragma unroll
                for (int in = 0; in < 4; ++in) acc[im][in] += a[im] * bb[in];
        }
        __syncthreads();
    }
#pragma unroll
    for (int im = 0; im < 8; ++im) {
        float4 o = make_float4(acc[im][0], acc[im][1], acc[im][2], acc[im][3]);
        *(float4*)(Cm + (size_t)(rowBase + ty * 8 + im) * N + colBase + tx * 4) = o;
    }
}

// W = wv @ wo  -> writes g_W (no host symbol lookup needed)
__global__ __launch_bounds__(256) void k_gemm_w(const float* __restrict__ wv,
                                                const float* __restrict__ wo) {
    gemm_core(wv, wo, g_W, DD, DD);
}

// out = g_vagg @ g_W
__global__ __launch_bounds__(256) void k_gemm_out(float* __restrict__ out) {
    gemm_core(g_vagg, g_W, out, DD, DD);
}

// ---------------- K6: Vagg[b,t,:] = sum_k w_k values[b,(t+d_k)%L,:] ----------
// grid (L, B), block 128 (float4 per thread)
__global__ void k_vagg(const float* __restrict__ values) {
    int t = blockIdx.x, b = blockIdx.y;
    __shared__ float w[KTOP];
    __shared__ int dl[KTOP];
    if (threadIdx.x < KTOP) { w[threadIdx.x] = g_wt[b * 8 + threadIdx.x]; dl[threadIdx.x] = g_dl[b * 8 + threadIdx.x]; }
    __syncthreads();
    int d4 = threadIdx.x;
    float4 acc = make_float4(0.f, 0.f, 0.f, 0.f);
#pragma unroll
    for (int k = 0; k < KTOP; ++k) {
        int src = (t + dl[k]) & (LL - 1);
        const float4* row = (const float4*)(values + ((size_t)b * LL + src) * DD);
        float4 v = row[d4];
        float wk = w[k];
        acc.x += wk * v.x; acc.y += wk * v.y; acc.z += wk * v.z; acc.w += wk * v.w;
    }
    ((float4*)(g_vagg + ((size_t)b * LL + t) * DD))[d4] = acc;
}

extern "C" void kernel_launch(void* const* d_in, const int* in_sizes, int n_in,
                              void* d_out, int out_size) {
    (void)in_sizes; (void)n_in; (void)out_size;
    const float* queries = (const float*)d_in[0];
    const float* keys    = (const float*)d_in[1];
    const float* values  = (const float*)d_in[2];
    const float* wq      = (const float*)d_in[3];
    const float* wk      = (const float*)d_in[4];
    const float* wv      = (const float*)d_in[5];
    const float* wo      = (const float*)d_in[6];
    float* out = (float*)d_out;

    // selection path
    k_qpart<<<dim3(BB, 2, 16), 256>>>(queries);
    k_rvec<<<BB, 512>>>(wq, wk);
    k_mc<<<dim3(LL / 8, BB), 256>>>(keys);
    k_topk<<<BB, 256>>>();

    // W = wv @ wo  (512x512x512)
    k_gemm_w<<<dim3(DD / 64, DD / 128), 256>>>(wv, wo);

    // blended values, then out = Vagg @ W  (8192x512x512)
    k_vagg<<<dim3(LL, BB), 128>>>(values);
    k_gemm_out<<<dim3(DD / 64, (BB * LL) / 128), 256>>>(out);
}